// round 1
// baseline (speedup 1.0000x reference)
#include <cuda_runtime.h>
#include <math.h>

#define BQ 64
#define NQ 2048
#define DQ 256
#define HQ 8
#define KDQ 32
#define VDQ 32
#define OQ 256
#define HV 256   // H * VD = flattened gate dim

// ---------------- scratch (static device arrays: no allocation) ----------------
__device__ float g_q[BQ * HQ * KDQ];                 // [B][H][KD] = [B][256]
__device__ float g_v[(size_t)BQ * NQ * VDQ];         // [B][N][VD]  16 MB
__device__ float g_logits[(size_t)BQ * HQ * NQ];     // [B][H][N]    4 MB
__device__ float g_wavg[BQ * HV];                    // [B][H*VD]
__device__ float g_gated[(size_t)BQ * NQ * HV];      // [B*N][256] 128 MB

// ---------------- K1: masked mean over N, then q = q_avg @ query_w * kd^-0.5 ----
__global__ void k1_qavg(const float* __restrict__ qd, const float* __restrict__ qm,
                        const float* __restrict__ qw) {
    int b = blockIdx.x, t = threadIdx.x;
    __shared__ float red[256];
    __shared__ float qavg[DQ];

    // mask sum over N
    float ms = 0.f;
    for (int n = t; n < NQ; n += 256) ms += qm[b * NQ + n];
    red[t] = ms;
    __syncthreads();
    for (int s = 128; s > 0; s >>= 1) {
        if (t < s) red[t] += red[t + s];
        __syncthreads();
    }
    float masksum = red[0] + 1e-10f;

    // masked sum of q_data for d = t
    const float* qdb = qd + (size_t)b * NQ * DQ + t;
    const float* qmb = qm + b * NQ;
    float acc = 0.f;
#pragma unroll 8
    for (int n = 0; n < NQ; n++) acc += qmb[n] * qdb[(size_t)n * DQ];
    qavg[t] = acc / masksum;
    __syncthreads();

    // q[b, h, kd] for t = h*32+kd
    float r = 0.f;
#pragma unroll 8
    for (int d = 0; d < DQ; d++) r += qavg[d] * qw[d * 256 + t];
    g_q[b * 256 + t] = r * 0.17677669529663687f;  // 32^-0.5
}

// ---------------- K2: k = m@key_w, v = m@value_w, logits = q.k + bias ----------
__global__ void k2_kv_logits(const float* __restrict__ md, const float* __restrict__ qm,
                             const float* __restrict__ kw, const float* __restrict__ vw) {
    int n0 = blockIdx.x * 128;
    int b  = blockIdx.y;
    int t  = threadIdx.x;
    int tc = t & 15, tr = t >> 4;

    __shared__ float As[128][33];   // A tile, later reused for k values
    __shared__ float Ws[32][65];    // weight K-chunk: [kk][c] c<32 key, c>=32 value
    __shared__ float qs[8][32];

    float acc[8][4];
#pragma unroll
    for (int i = 0; i < 8; i++)
#pragma unroll
        for (int j = 0; j < 4; j++) acc[i][j] = 0.f;

    const float* Abase = md + ((size_t)b * NQ + n0) * DQ;

    for (int kc = 0; kc < 8; kc++) {
#pragma unroll
        for (int i = 0; i < 4; i++) {
            int id = t + i * 256;
            int row = id >> 3, f4 = id & 7;
            float4 v4 = *(const float4*)(Abase + (size_t)row * DQ + kc * 32 + f4 * 4);
            As[row][f4 * 4 + 0] = v4.x; As[row][f4 * 4 + 1] = v4.y;
            As[row][f4 * 4 + 2] = v4.z; As[row][f4 * 4 + 3] = v4.w;
        }
#pragma unroll
        for (int i = 0; i < 8; i++) {
            int id = t + i * 256;
            int kk = id >> 6, c = id & 63;
            Ws[kk][c] = (c < 32) ? kw[(kc * 32 + kk) * 32 + c]
                                 : vw[(kc * 32 + kk) * 32 + (c - 32)];
        }
        __syncthreads();
#pragma unroll
        for (int kk = 0; kk < 32; kk++) {
            float bv[4];
#pragma unroll
            for (int j = 0; j < 4; j++) bv[j] = Ws[kk][tc * 4 + j];
#pragma unroll
            for (int i = 0; i < 8; i++) {
                float a = As[tr * 8 + i][kk];
#pragma unroll
                for (int j = 0; j < 4; j++) acc[i][j] += a * bv[j];
            }
        }
        __syncthreads();
    }

    // q into smem
    qs[t >> 5][t & 31] = g_q[b * 256 + t];

    // write v to global, keep k in smem (reuse As)
#pragma unroll
    for (int i = 0; i < 8; i++) {
        int row = tr * 8 + i;
#pragma unroll
        for (int j = 0; j < 4; j++) {
            int c = tc * 4 + j;
            if (c < 32) As[row][c] = acc[i][j];
            else        g_v[((size_t)b * NQ + n0 + row) * VDQ + (c - 32)] = acc[i][j];
        }
    }
    __syncthreads();

    // logits: 128 n x 8 h = 1024 per block, 4 per thread
#pragma unroll
    for (int ii = 0; ii < 4; ii++) {
        int idx = ii * 256 + t;
        int h = idx & 7, n = idx >> 3;
        float s = 0.f;
#pragma unroll
        for (int kd = 0; kd < 32; kd++) s += qs[h][kd] * As[n][kd];
        float maskv = qm[b * NQ + n0 + n];
        g_logits[((size_t)b * HQ + h) * NQ + n0 + n] = s + 1e9f * (maskv - 1.0f);
    }
}

// ---------------- K3: softmax over N + weighted_avg -----------------------------
__global__ void k3_softmax_wavg() {
    int b = blockIdx.x, t = threadIdx.x;
    __shared__ float sl[NQ];      // 8 KB
    __shared__ float red[256];
    __shared__ float pacc[8][32];

    for (int h = 0; h < HQ; h++) {
        const float* lrow = g_logits + ((size_t)b * HQ + h) * NQ;
        float m = -1e30f;
#pragma unroll
        for (int i = 0; i < 8; i++) {
            float v = lrow[t + i * 256];
            sl[t + i * 256] = v;
            m = fmaxf(m, v);
        }
        red[t] = m;
        __syncthreads();
        for (int s = 128; s > 0; s >>= 1) {
            if (t < s) red[t] = fmaxf(red[t], red[t + s]);
            __syncthreads();
        }
        float mx = red[0];
        __syncthreads();
        float lsum = 0.f;
#pragma unroll
        for (int i = 0; i < 8; i++) {
            float e = __expf(sl[t + i * 256] - mx);
            sl[t + i * 256] = e;
            lsum += e;
        }
        red[t] = lsum;
        __syncthreads();
        for (int s = 128; s > 0; s >>= 1) {
            if (t < s) red[t] += red[t + s];
            __syncthreads();
        }
        float S = red[0];

        // weighted avg: warp p handles n = p, p+8, ...; lane = vd
        int vd = t & 31, part = t >> 5;
        float acc = 0.f;
        for (int n = part; n < NQ; n += 8)
            acc += sl[n] * g_v[((size_t)b * NQ + n) * VDQ + vd];
        pacc[part][vd] = acc;
        __syncthreads();
        if (t < 32) {
            float s2 = 0.f;
#pragma unroll
            for (int p = 0; p < 8; p++) s2 += pacc[p][t];
            g_wavg[b * HV + h * 32 + t] = s2 / S;
        }
        __syncthreads();
    }
}

// ---------------- K4a: gate = sigmoid(q_data @ gating_w + gb) * wavg ------------
__global__ void k4a_gate(const float* __restrict__ qd, const float* __restrict__ gw,
                         const float* __restrict__ gb) {
    int r0 = blockIdx.x * 128, c0 = blockIdx.y * 64;
    int t = threadIdx.x;
    int tc = t & 15, tr = t >> 4;
    __shared__ float As[128][33];
    __shared__ float Bs[32][65];

    float acc[8][4];
#pragma unroll
    for (int i = 0; i < 8; i++)
#pragma unroll
        for (int j = 0; j < 4; j++) acc[i][j] = 0.f;

    const float* Abase = qd + (size_t)r0 * DQ;
    for (int kc = 0; kc < 8; kc++) {
#pragma unroll
        for (int i = 0; i < 4; i++) {
            int id = t + i * 256;
            int row = id >> 3, f4 = id & 7;
            float4 v4 = *(const float4*)(Abase + (size_t)row * DQ + kc * 32 + f4 * 4);
            As[row][f4 * 4 + 0] = v4.x; As[row][f4 * 4 + 1] = v4.y;
            As[row][f4 * 4 + 2] = v4.z; As[row][f4 * 4 + 3] = v4.w;
        }
#pragma unroll
        for (int i = 0; i < 8; i++) {
            int id = t + i * 256;
            int kk = id >> 6, c = id & 63;
            Bs[kk][c] = gw[(size_t)(kc * 32 + kk) * HV + c0 + c];
        }
        __syncthreads();
#pragma unroll
        for (int kk = 0; kk < 32; kk++) {
            float bv[4];
#pragma unroll
            for (int j = 0; j < 4; j++) bv[j] = Bs[kk][tc * 4 + j];
#pragma unroll
            for (int i = 0; i < 8; i++) {
                float a = As[tr * 8 + i][kk];
#pragma unroll
                for (int j = 0; j < 4; j++) acc[i][j] += a * bv[j];
            }
        }
        __syncthreads();
    }

    int b = r0 >> 11;  // 2048 rows per batch
#pragma unroll
    for (int i = 0; i < 8; i++) {
        size_t r = r0 + tr * 8 + i;
#pragma unroll
        for (int j = 0; j < 4; j++) {
            int c = c0 + tc * 4 + j;
            float x = acc[i][j] + gb[c];
            float g = 1.0f / (1.0f + __expf(-x));
            g_gated[r * HV + c] = g * g_wavg[b * HV + c];
        }
    }
}

// ---------------- K4b: out = gated @ output_w + ob -------------------------------
__global__ void k4b_out(const float* __restrict__ ow, const float* __restrict__ ob,
                        float* __restrict__ out) {
    int r0 = blockIdx.x * 128, c0 = blockIdx.y * 64;
    int t = threadIdx.x;
    int tc = t & 15, tr = t >> 4;
    __shared__ float As[128][33];
    __shared__ float Bs[32][65];

    float acc[8][4];
#pragma unroll
    for (int i = 0; i < 8; i++)
#pragma unroll
        for (int j = 0; j < 4; j++) acc[i][j] = 0.f;

    const float* Abase = g_gated + (size_t)r0 * HV;
    for (int kc = 0; kc < 8; kc++) {
#pragma unroll
        for (int i = 0; i < 4; i++) {
            int id = t + i * 256;
            int row = id >> 3, f4 = id & 7;
            float4 v4 = *(const float4*)(Abase + (size_t)row * HV + kc * 32 + f4 * 4);
            As[row][f4 * 4 + 0] = v4.x; As[row][f4 * 4 + 1] = v4.y;
            As[row][f4 * 4 + 2] = v4.z; As[row][f4 * 4 + 3] = v4.w;
        }
#pragma unroll
        for (int i = 0; i < 8; i++) {
            int id = t + i * 256;
            int kk = id >> 6, c = id & 63;
            Bs[kk][c] = ow[(size_t)(kc * 32 + kk) * OQ + c0 + c];
        }
        __syncthreads();
#pragma unroll
        for (int kk = 0; kk < 32; kk++) {
            float bv[4];
#pragma unroll
            for (int j = 0; j < 4; j++) bv[j] = Bs[kk][tc * 4 + j];
#pragma unroll
            for (int i = 0; i < 8; i++) {
                float a = As[tr * 8 + i][kk];
#pragma unroll
                for (int j = 0; j < 4; j++) acc[i][j] += a * bv[j];
            }
        }
        __syncthreads();
    }

#pragma unroll
    for (int i = 0; i < 8; i++) {
        size_t r = r0 + tr * 8 + i;
#pragma unroll
        for (int j = 0; j < 4; j++) {
            int c = c0 + tc * 4 + j;
            out[r * OQ + c] = acc[i][j] + ob[c];
        }
    }
}

// ---------------- launcher ------------------------------------------------------
extern "C" void kernel_launch(void* const* d_in, const int* in_sizes, int n_in,
                              void* d_out, int out_size) {
    const float* qd = (const float*)d_in[0];  // q_data  [B,N,D]
    const float* md = (const float*)d_in[1];  // m_data  [B,N,D]
    const float* qm = (const float*)d_in[2];  // q_mask  [B,N,1]
    const float* qw = (const float*)d_in[3];  // query_w [D,H,KD]
    const float* kw = (const float*)d_in[4];  // key_w   [D,KD]
    const float* vw = (const float*)d_in[5];  // value_w [D,VD]
    const float* gw = (const float*)d_in[6];  // gating_w [D,H,VD]
    const float* gb = (const float*)d_in[7];  // gating_b [H,VD]
    const float* ow = (const float*)d_in[8];  // output_w [H,VD,O]
    const float* ob = (const float*)d_in[9];  // output_b [O]
    float* out = (float*)d_out;               // [B,N,O] fp32

    k1_qavg<<<BQ, 256>>>(qd, qm, qw);
    k2_kv_logits<<<dim3(NQ / 128, BQ), 256>>>(md, qm, kw, vw);
    k3_softmax_wavg<<<BQ, 256>>>();
    k4a_gate<<<dim3((BQ * NQ) / 128, HV / 64), 256>>>(qd, gw, gb);
    k4b_out<<<dim3((BQ * NQ) / 128, OQ / 64), 256>>>(ow, ob, out);
}

// round 3
// speedup vs baseline: 1.9310x; 1.9310x over previous
#include <cuda_runtime.h>
#include <math.h>

#define BQ 64
#define NQ 2048
#define DQ 256
#define HQ 8
#define KDQ 32
#define VDQ 32
#define OQ 256
#define HV 256   // H * VD = flattened gate dim

// ---------------- scratch (static device arrays: no allocation) ----------------
__device__ float g_q[BQ * HQ * KDQ];                 // [B][H][KD] = [B][256]
__device__ float g_v[(size_t)BQ * NQ * VDQ];         // [B][N][VD]  16 MB
__device__ float g_logits[(size_t)BQ * HQ * NQ];     // [B][H][N]    4 MB
__device__ float g_wavg[BQ * HV];                    // [B][H*VD]
__device__ float g_gated[(size_t)BQ * NQ * HV];      // [B*N][256] 128 MB

// ---------------- tf32 helpers --------------------------------------------------
__device__ __forceinline__ unsigned f2tf(float f) {
    unsigned u;
    asm("cvt.rna.tf32.f32 %0, %1;" : "=r"(u) : "f"(f));
    return u;
}

__device__ __forceinline__ void mma_tf32(float* d, const unsigned* a, const unsigned* b) {
    asm volatile(
        "mma.sync.aligned.m16n8k8.row.col.f32.tf32.tf32.f32 "
        "{%0,%1,%2,%3}, {%4,%5,%6,%7}, {%8,%9}, {%0,%1,%2,%3};\n"
        : "+f"(d[0]), "+f"(d[1]), "+f"(d[2]), "+f"(d[3])
        : "r"(a[0]), "r"(a[1]), "r"(a[2]), "r"(a[3]), "r"(b[0]), "r"(b[1]));
}

// ---------------- K1: masked mean over N, then q = q_avg @ query_w * kd^-0.5 ----
__global__ void k1_qavg(const float* __restrict__ qd, const float* __restrict__ qm,
                        const float* __restrict__ qw) {
    int b = blockIdx.x, t = threadIdx.x;
    __shared__ float red[256];
    __shared__ float qavg[DQ];

    float ms = 0.f;
    for (int n = t; n < NQ; n += 256) ms += qm[b * NQ + n];
    red[t] = ms;
    __syncthreads();
    for (int s = 128; s > 0; s >>= 1) {
        if (t < s) red[t] += red[t + s];
        __syncthreads();
    }
    float masksum = red[0] + 1e-10f;

    const float* qdb = qd + (size_t)b * NQ * DQ + t;
    const float* qmb = qm + b * NQ;
    float acc = 0.f;
#pragma unroll 8
    for (int n = 0; n < NQ; n++) acc += qmb[n] * qdb[(size_t)n * DQ];
    qavg[t] = acc / masksum;
    __syncthreads();

    float r = 0.f;
#pragma unroll 8
    for (int d = 0; d < DQ; d++) r += qavg[d] * qw[d * 256 + t];
    g_q[b * 256 + t] = r * 0.17677669529663687f;  // 32^-0.5
}

// ---------------- K2: k = m@key_w, v = m@value_w, logits = q.k + bias ----------
__global__ void k2_kv_logits(const float* __restrict__ md, const float* __restrict__ qm,
                             const float* __restrict__ kw, const float* __restrict__ vw) {
    int n0 = blockIdx.x * 128;
    int b  = blockIdx.y;
    int t  = threadIdx.x;
    int tc = t & 15, tr = t >> 4;

    __shared__ float As[128][33];   // A tile, later reused for k values
    __shared__ float Ws[32][65];    // weight K-chunk
    __shared__ float qs[8][32];

    float acc[8][4];
#pragma unroll
    for (int i = 0; i < 8; i++)
#pragma unroll
        for (int j = 0; j < 4; j++) acc[i][j] = 0.f;

    const float* Abase = md + ((size_t)b * NQ + n0) * DQ;

    for (int kc = 0; kc < 8; kc++) {
#pragma unroll
        for (int i = 0; i < 4; i++) {
            int id = t + i * 256;
            int row = id >> 3, f4 = id & 7;
            float4 v4 = *(const float4*)(Abase + (size_t)row * DQ + kc * 32 + f4 * 4);
            As[row][f4 * 4 + 0] = v4.x; As[row][f4 * 4 + 1] = v4.y;
            As[row][f4 * 4 + 2] = v4.z; As[row][f4 * 4 + 3] = v4.w;
        }
#pragma unroll
        for (int i = 0; i < 8; i++) {
            int id = t + i * 256;
            int kk = id >> 6, c = id & 63;
            Ws[kk][c] = (c < 32) ? kw[(kc * 32 + kk) * 32 + c]
                                 : vw[(kc * 32 + kk) * 32 + (c - 32)];
        }
        __syncthreads();
#pragma unroll
        for (int kk = 0; kk < 32; kk++) {
            float bv[4];
#pragma unroll
            for (int j = 0; j < 4; j++) bv[j] = Ws[kk][tc * 4 + j];
#pragma unroll
            for (int i = 0; i < 8; i++) {
                float a = As[tr * 8 + i][kk];
#pragma unroll
                for (int j = 0; j < 4; j++) acc[i][j] += a * bv[j];
            }
        }
        __syncthreads();
    }

    qs[t >> 5][t & 31] = g_q[b * 256 + t];

#pragma unroll
    for (int i = 0; i < 8; i++) {
        int row = tr * 8 + i;
#pragma unroll
        for (int j = 0; j < 4; j++) {
            int c = tc * 4 + j;
            if (c < 32) As[row][c] = acc[i][j];
            else        g_v[((size_t)b * NQ + n0 + row) * VDQ + (c - 32)] = acc[i][j];
        }
    }
    __syncthreads();

#pragma unroll
    for (int ii = 0; ii < 4; ii++) {
        int idx = ii * 256 + t;
        int h = idx & 7, n = idx >> 3;
        float s = 0.f;
#pragma unroll
        for (int kd = 0; kd < 32; kd++) s += qs[h][kd] * As[n][kd];
        float maskv = qm[b * NQ + n0 + n];
        g_logits[((size_t)b * HQ + h) * NQ + n0 + n] = s + 1e9f * (maskv - 1.0f);
    }
}

// ---------------- K3: softmax over N + weighted_avg (single pass over v) --------
__global__ void k3_softmax_wavg() {
    int b = blockIdx.x, t = threadIdx.x;
    int lane = t & 31, wid = t >> 5;
    __shared__ float mxs[8], invS[8];
    __shared__ float vsm[128][33];
    __shared__ float lgs[8][128];

    // Phase 1: warp `wid` computes max & expsum for head `wid`
    {
        const float* lrow = g_logits + ((size_t)b * HQ + wid) * NQ;
        float m = -1e30f;
        for (int n = lane; n < NQ; n += 32) m = fmaxf(m, lrow[n]);
#pragma unroll
        for (int o = 16; o > 0; o >>= 1) m = fmaxf(m, __shfl_xor_sync(0xffffffffu, m, o));
        float s = 0.f;
        for (int n = lane; n < NQ; n += 32) s += __expf(lrow[n] - m);
#pragma unroll
        for (int o = 16; o > 0; o >>= 1) s += __shfl_xor_sync(0xffffffffu, s, o);
        if (lane == 0) { mxs[wid] = m; invS[wid] = 1.0f / s; }
    }
    __syncthreads();

    // Phase 2: accumulate all 8 heads reading v once
    int h = wid, vd = lane;           // thread owns (h, vd)
    float acc = 0.f;

    for (int c = 0; c < NQ / 128; c++) {
        // load v chunk [128][32]
#pragma unroll
        for (int i = 0; i < 16; i++) {
            int s = t + i * 256;
            int row = s >> 5, col = s & 31;
            vsm[row][col] = g_v[((size_t)b * NQ + c * 128 + row) * VDQ + col];
        }
        // load logits chunk [8][128]
#pragma unroll
        for (int i = 0; i < 4; i++) {
            int s = t + i * 256;
            int hh = s >> 7, n = s & 127;
            lgs[hh][n] = g_logits[((size_t)b * HQ + hh) * NQ + c * 128 + n];
        }
        __syncthreads();
#pragma unroll
        for (int i = 0; i < 4; i++) {
            int s = t + i * 256;
            int hh = s >> 7, n = s & 127;
            lgs[hh][n] = __expf(lgs[hh][n] - mxs[hh]);
        }
        __syncthreads();
#pragma unroll 8
        for (int n = 0; n < 128; n++)
            acc += lgs[h][n] * vsm[n][vd];
        __syncthreads();
    }
    g_wavg[b * HV + h * 32 + vd] = acc * invS[h];
}

// ---------------- tf32 MMA GEMM body (128x128 tile, K=256) ----------------------
// A: row-major [*, 256]; B: row-major [256, 256]
// EPI = 0: gate epilogue (k4a); EPI = 1: output epilogue (k4b)
template <int EPI>
__global__ __launch_bounds__(256) void k4_mma(const float* __restrict__ Ag,
                                              const float* __restrict__ Bg,
                                              const float* __restrict__ bias,
                                              float* __restrict__ Cg) {
    const int r0 = blockIdx.x * 128;
    const int c0 = blockIdx.y * 128;
    const int t = threadIdx.x;
    const int lane = t & 31, wid = t >> 5;
    const int wm = wid >> 1, wn = wid & 1;   // 4 x 2 warp grid
    const int gr = lane >> 2, tig = lane & 3;

    __shared__ unsigned As[128][36];
    __shared__ unsigned Bs[32][132];

    float acc[2][8][4];
#pragma unroll
    for (int mi = 0; mi < 2; mi++)
#pragma unroll
        for (int ni = 0; ni < 8; ni++)
#pragma unroll
            for (int j = 0; j < 4; j++) acc[mi][ni][j] = 0.f;

    for (int kc = 0; kc < 8; kc++) {
        // A tile: 128 rows x 32 cols
#pragma unroll
        for (int i = 0; i < 4; i++) {
            int s = t + i * 256;
            int row = s >> 3, c4 = s & 7;
            float4 v = *(const float4*)(Ag + (size_t)(r0 + row) * 256 + kc * 32 + c4 * 4);
            As[row][c4 * 4 + 0] = f2tf(v.x);
            As[row][c4 * 4 + 1] = f2tf(v.y);
            As[row][c4 * 4 + 2] = f2tf(v.z);
            As[row][c4 * 4 + 3] = f2tf(v.w);
        }
        // B tile: 32 rows x 128 cols
#pragma unroll
        for (int i = 0; i < 4; i++) {
            int s = t + i * 256;
            int k = s >> 5, n4 = s & 31;
            float4 v = *(const float4*)(Bg + (size_t)(kc * 32 + k) * 256 + c0 + n4 * 4);
            Bs[k][n4 * 4 + 0] = f2tf(v.x);
            Bs[k][n4 * 4 + 1] = f2tf(v.y);
            Bs[k][n4 * 4 + 2] = f2tf(v.z);
            Bs[k][n4 * 4 + 3] = f2tf(v.w);
        }
        __syncthreads();

#pragma unroll
        for (int ks = 0; ks < 4; ks++) {
            const int k0 = ks * 8;
            unsigned af[2][4];
#pragma unroll
            for (int mi = 0; mi < 2; mi++) {
                int rb = wm * 32 + mi * 16;
                af[mi][0] = As[rb + gr][k0 + tig];
                af[mi][1] = As[rb + gr + 8][k0 + tig];
                af[mi][2] = As[rb + gr][k0 + tig + 4];
                af[mi][3] = As[rb + gr + 8][k0 + tig + 4];
            }
            unsigned bf[8][2];
#pragma unroll
            for (int ni = 0; ni < 8; ni++) {
                int cb = wn * 64 + ni * 8 + gr;
                bf[ni][0] = Bs[k0 + tig][cb];
                bf[ni][1] = Bs[k0 + tig + 4][cb];
            }
#pragma unroll
            for (int mi = 0; mi < 2; mi++)
#pragma unroll
                for (int ni = 0; ni < 8; ni++)
                    mma_tf32(acc[mi][ni], af[mi], bf[ni]);
        }
        __syncthreads();
    }

    // epilogue
#pragma unroll
    for (int mi = 0; mi < 2; mi++) {
#pragma unroll
        for (int ni = 0; ni < 8; ni++) {
            int row = r0 + wm * 32 + mi * 16 + gr;
            int col = c0 + wn * 64 + ni * 8 + tig * 2;
#pragma unroll
            for (int half = 0; half < 2; half++) {
                int rr = row + half * 8;
                float x0 = acc[mi][ni][half * 2 + 0];
                float x1 = acc[mi][ni][half * 2 + 1];
                if (EPI == 0) {
                    int b = rr >> 11;
                    float b0 = bias[col], b1 = bias[col + 1];
                    float g0 = 1.0f / (1.0f + __expf(-(x0 + b0)));
                    float g1 = 1.0f / (1.0f + __expf(-(x1 + b1)));
                    float2 w = *(const float2*)&g_wavg[b * HV + col];
                    float2 o;
                    o.x = g0 * w.x;
                    o.y = g1 * w.y;
                    *(float2*)&Cg[(size_t)rr * 256 + col] = o;
                } else {
                    float2 o;
                    o.x = x0 + bias[col];
                    o.y = x1 + bias[col + 1];
                    *(float2*)&Cg[(size_t)rr * 256 + col] = o;
                }
            }
        }
    }
}

// ---------------- launcher ------------------------------------------------------
extern "C" void kernel_launch(void* const* d_in, const int* in_sizes, int n_in,
                              void* d_out, int out_size) {
    const float* qd = (const float*)d_in[0];  // q_data  [B,N,D]
    const float* md = (const float*)d_in[1];  // m_data  [B,N,D]
    const float* qm = (const float*)d_in[2];  // q_mask  [B,N,1]
    const float* qw = (const float*)d_in[3];  // query_w [D,H,KD]
    const float* kw = (const float*)d_in[4];  // key_w   [D,KD]
    const float* vw = (const float*)d_in[5];  // value_w [D,VD]
    const float* gw = (const float*)d_in[6];  // gating_w [D,H,VD]
    const float* gb = (const float*)d_in[7];  // gating_b [H,VD]
    const float* ow = (const float*)d_in[8];  // output_w [H,VD,O]
    const float* ob = (const float*)d_in[9];  // output_b [O]
    float* out = (float*)d_out;               // [B,N,O] fp32

    float* gated = nullptr;
    cudaGetSymbolAddress((void**)&gated, g_gated);

    k1_qavg<<<BQ, 256>>>(qd, qm, qw);
    k2_kv_logits<<<dim3(NQ / 128, BQ), 256>>>(md, qm, kw, vw);
    k3_softmax_wavg<<<BQ, 256>>>();
    k4_mma<0><<<dim3((BQ * NQ) / 128, HV / 128), 256>>>(qd, gw, gb, gated);
    k4_mma<1><<<dim3((BQ * NQ) / 128, OQ / 128), 256>>>(gated, ow, ob, out);
}